// round 2
// baseline (speedup 1.0000x reference)
#include <cuda_runtime.h>
#include <math.h>

#define NPTS   2048
#define IDIM   16
#define HDIM   32
#define JSPLIT 37
#define JCHUNK 56
#define TILE_I 128

// ---------------- device scratch ----------------
__device__ float4 g_pts4[NPTS];
__device__ float4 g_nrm4[NPTS];
__device__ float  g_z   [NPTS * HDIM];
__device__ float  g_partial[JSPLIT][NPTS * HDIM];
__device__ float  g_stats[8];   // mu[0..3], rstd[4..7]

__device__ __forceinline__ float leakyf(float x) { return x >= 0.f ? x : 0.2f * x; }

// ---------------- packed f32x2 helpers (sm_103a) ----------------
__device__ __forceinline__ float2 fma2(float2 a, float2 b, float2 c) {
    float2 d;
    asm("{\n\t"
        ".reg .b64 ra, rb, rc;\n\t"
        "mov.b64 ra, {%2,%3};\n\t"
        "mov.b64 rb, {%4,%5};\n\t"
        "mov.b64 rc, {%6,%7};\n\t"
        "fma.rn.f32x2 rc, ra, rb, rc;\n\t"
        "mov.b64 {%0,%1}, rc;\n\t"
        "}"
        : "=f"(d.x), "=f"(d.y)
        : "f"(a.x), "f"(a.y), "f"(b.x), "f"(b.y), "f"(c.x), "f"(c.y));
    return d;
}

__device__ __forceinline__ float2 mul2(float2 a, float2 b) {
    float2 d;
    asm("{\n\t"
        ".reg .b64 ra, rb;\n\t"
        "mov.b64 ra, {%2,%3};\n\t"
        "mov.b64 rb, {%4,%5};\n\t"
        "mul.rn.f32x2 ra, ra, rb;\n\t"
        "mov.b64 {%0,%1}, ra;\n\t"
        "}"
        : "=f"(d.x), "=f"(d.y)
        : "f"(a.x), "f"(a.y), "f"(b.x), "f"(b.y));
    return d;
}

// ---------------- net_in + prep fused ----------------
__global__ void k_netin(const float* __restrict__ points, const float* __restrict__ nuv,
                        const float* __restrict__ x,
                        const float* __restrict__ W1, const float* __restrict__ b1,
                        const float* __restrict__ W2, const float* __restrict__ b2) {
    __shared__ float sW1[HDIM * IDIM], sW2[HDIM * HDIM], sb1[HDIM], sb2[HDIM];
    int tid = threadIdx.x;
    for (int k = tid; k < HDIM * IDIM; k += TILE_I) sW1[k] = W1[k];
    for (int k = tid; k < HDIM * HDIM; k += TILE_I) sW2[k] = W2[k];
    if (tid < HDIM) { sb1[tid] = b1[tid]; sb2[tid] = b2[tid]; }
    __syncthreads();

    int n = blockIdx.x * TILE_I + tid;

    const float s = 0.07856742013183862f;  // 1/(sqrt(2)*9)
    g_pts4[n] = make_float4(points[n * 3] * s, points[n * 3 + 1] * s, points[n * 3 + 2] * s, 0.f);
    g_nrm4[n] = make_float4(nuv[n * 9], nuv[n * 9 + 1], nuv[n * 9 + 2], 0.f);

    float xi[IDIM];
#pragma unroll
    for (int i = 0; i < IDIM; i++) xi[i] = x[n * IDIM + i];

    float z1[HDIM];
#pragma unroll
    for (int h = 0; h < HDIM; h++) {
        float acc = sb1[h];
#pragma unroll
        for (int i = 0; i < IDIM; i++) acc = fmaf(sW1[h * IDIM + i], xi[i], acc);
        z1[h] = leakyf(acc);
    }
#pragma unroll
    for (int h = 0; h < HDIM; h++) {
        float acc = sb2[h];
#pragma unroll
        for (int c = 0; c < HDIM; c++) acc = fmaf(sW2[h * HDIM + c], z1[c], acc);
        g_z[n * HDIM + h] = leakyf(acc);
    }
}

// ---------------- group-norm stats (coalesced, 1024 threads, 1 block) ----------------
__global__ void k_gstats(const float* __restrict__ z) {
    __shared__ double sh_s[1024], sh_q[1024];
    int tid = threadIdx.x;
    int c = tid & 31;          // channel, fixed per thread -> coalesced
    int r0 = tid >> 5;         // starting row
    double s = 0.0, q = 0.0;
    for (int it = 0; it < NPTS / 32; it++) {
        float v = z[(r0 + 32 * it) * HDIM + c];
        s += (double)v;
        q += (double)v * (double)v;
    }
    sh_s[tid] = s; sh_q[tid] = q;
    __syncthreads();
    if (tid < 32) {
        double S = 0.0, Q = 0.0;
        for (int m = 0; m < 32; m++) { S += sh_s[tid + 32 * m]; Q += sh_q[tid + 32 * m]; }
        sh_s[tid] = S; sh_q[tid] = Q;
    }
    __syncthreads();
    if (tid < 4) {
        double S = 0.0, Q = 0.0;
        for (int cc = tid * 8; cc < tid * 8 + 8; cc++) { S += sh_s[cc]; Q += sh_q[cc]; }
        double cntd = (double)NPTS * 8.0;
        double mu = S / cntd;
        double var = Q / cntd - mu * mu;
        g_stats[tid]     = (float)mu;
        g_stats[4 + tid] = (float)(1.0 / sqrt(var + 1e-5));
    }
}

// ---------------- apply group norm (final output only) ----------------
__global__ void k_gnorm(const float* __restrict__ z, const float* __restrict__ gamma,
                        const float* __restrict__ beta, float* __restrict__ out) {
    int idx = blockIdx.x * blockDim.x + threadIdx.x;
    if (idx >= NPTS * HDIM) return;
    int c = idx & (HDIM - 1);
    int g = c >> 3;
    out[idx] = (z[idx] - g_stats[g]) * g_stats[4 + g] * gamma[c] + beta[c];
}

// ---------------- pairwise interaction (packed f32x2, gnorm-in fused) ----------------
__global__ void __launch_bounds__(TILE_I, 4)
k_pair(const float* __restrict__ nuv,
       const float* __restrict__ A1, const float* __restrict__ B1,
       const float* __restrict__ A2, const float* __restrict__ B2,
       const float* __restrict__ gamma, const float* __restrict__ beta) {
    __shared__ float4 sP[JCHUNK], sN[JCHUNK];
    __shared__ float  sF[JCHUNK][HDIM];
    __shared__ float4 sA2p4[16][4];   // [hp][cq]: (A2[2hp][c],A2[2hp+1][c],A2[2hp][c+1],A2[2hp+1][c+1])
    __shared__ float2 sB2p[16];
    __shared__ float4 sA1[8];         // (a1_c0, a1_c1, a1_c2, b1_c)
    __shared__ float  smu[4], srs[4];

    int tid = threadIdx.x;
    int j0  = blockIdx.y * JCHUNK;
    int cnt = min(JCHUNK, NPTS - j0);

    if (tid < 4)               { smu[tid] = g_stats[tid]; srs[tid] = g_stats[4 + tid]; }
    if (tid >= 8 && tid < 16)  { int c = tid - 8;  sA1[c]  = make_float4(A1[c*3], A1[c*3+1], A1[c*3+2], B1[c]); }
    if (tid >= 16 && tid < 32) { int hp = tid - 16; sB2p[hp] = make_float2(B2[2*hp], B2[2*hp+1]); }
    __syncthreads();   // smu needed below

    for (int k = tid; k < cnt; k += TILE_I) { sP[k] = g_pts4[j0 + k]; sN[k] = g_nrm4[j0 + k]; }
    {
        int hp = tid >> 3, c = tid & 7;   // 128 threads cover all 16*8 pairs
        ((float2*)sA2p4)[hp * 8 + c] = make_float2(A2[(2*hp) * 8 + c], A2[(2*hp+1) * 8 + c]);
    }
    for (int k = tid; k < cnt * HDIM; k += TILE_I) {
        int r = k >> 5, c = k & 31, g = c >> 3;
        sF[r][c] = (g_z[(j0 + r) * HDIM + c] - smu[g]) * srs[g] * gamma[c] + beta[c];
    }
    __syncthreads();

    int i = blockIdx.x * TILE_I + tid;
    float4 p4 = g_pts4[i];
    float4 n4 = g_nrm4[i];
    float u[9];
#pragma unroll
    for (int k = 0; k < 9; k++) u[k] = nuv[i * 9 + k];

    float2 acc[16];
#pragma unroll
    for (int hp = 0; hp < 16; hp++) acc[hp] = make_float2(0.f, 0.f);

    for (int jj = 0; jj < cnt; jj += 2) {
        float2 xcd[2][8];
        float2 wd[2];
#pragma unroll
        for (int t2 = 0; t2 < 2; t2++) {
            int j = jj + t2;
            float4 pj = sP[j], nj = sN[j];
            float dx = pj.x - p4.x, dy = pj.y - p4.y, dz = pj.z - p4.z;
            float sq  = fmaf(dx, dx, fmaf(dy, dy, dz * dz));
            float dot = fmaf(n4.x, nj.x, fmaf(n4.y, nj.y, n4.z * nj.z));
            float t   = 2.f - dot;
            float w   = __expf(-(sq * t) * t);
            wd[t2] = make_float2(w, w);

            float X0 = fmaf(u[0], dx, fmaf(u[1], dy, u[2] * dz));
            float X1 = fmaf(u[3], dx, fmaf(u[4], dy, u[5] * dz));
            float X2 = fmaf(u[6], dx, fmaf(u[7], dy, u[8] * dz));
#pragma unroll
            for (int c = 0; c < 8; c++) {
                float4 a = sA1[c];
                float s = fmaf(a.x, X0, fmaf(a.y, X1, fmaf(a.z, X2, a.w)));
                s = fmaxf(s, 0.f);
                xcd[t2][c] = make_float2(s, s);
            }
        }

        const float4* f0r = (const float4*)sF[jj];
        const float4* f1r = (const float4*)sF[jj + 1];
#pragma unroll
        for (int hq = 0; hq < 8; hq++) {
            float4 f0q = f0r[hq];
            float4 f1q = f1r[hq];
#pragma unroll
            for (int hh = 0; hh < 2; hh++) {
                int hp = hq * 2 + hh;
                float4 aA = sA2p4[hp][0];
                float4 aB = sA2p4[hp][1];
                float4 aC = sA2p4[hp][2];
                float4 aD = sA2p4[hp][3];
                float2 b2 = sB2p[hp];
                float2 f0 = hh ? make_float2(f0q.z, f0q.w) : make_float2(f0q.x, f0q.y);
                float2 f1 = hh ? make_float2(f1q.z, f1q.w) : make_float2(f1q.x, f1q.y);

                // j = jj
                float2 s0 = b2;
                s0 = fma2(make_float2(aA.x, aA.y), xcd[0][0], s0);
                s0 = fma2(make_float2(aA.z, aA.w), xcd[0][1], s0);
                s0 = fma2(make_float2(aB.x, aB.y), xcd[0][2], s0);
                s0 = fma2(make_float2(aB.z, aB.w), xcd[0][3], s0);
                s0 = fma2(make_float2(aC.x, aC.y), xcd[0][4], s0);
                s0 = fma2(make_float2(aC.z, aC.w), xcd[0][5], s0);
                s0 = fma2(make_float2(aD.x, aD.y), xcd[0][6], s0);
                s0 = fma2(make_float2(aD.z, aD.w), xcd[0][7], s0);
                s0.x = fmaxf(s0.x, 0.f); s0.y = fmaxf(s0.y, 0.f);
                float2 wf0 = mul2(wd[0], f0);
                acc[hp] = fma2(s0, wf0, acc[hp]);

                // j = jj+1
                float2 s1 = b2;
                s1 = fma2(make_float2(aA.x, aA.y), xcd[1][0], s1);
                s1 = fma2(make_float2(aA.z, aA.w), xcd[1][1], s1);
                s1 = fma2(make_float2(aB.x, aB.y), xcd[1][2], s1);
                s1 = fma2(make_float2(aB.z, aB.w), xcd[1][3], s1);
                s1 = fma2(make_float2(aC.x, aC.y), xcd[1][4], s1);
                s1 = fma2(make_float2(aC.z, aC.w), xcd[1][5], s1);
                s1 = fma2(make_float2(aD.x, aD.y), xcd[1][6], s1);
                s1 = fma2(make_float2(aD.z, aD.w), xcd[1][7], s1);
                s1.x = fmaxf(s1.x, 0.f); s1.y = fmaxf(s1.y, 0.f);
                float2 wf1 = mul2(wd[1], f1);
                acc[hp] = fma2(s1, wf1, acc[hp]);
            }
        }
    }

    float4* outp = (float4*)&g_partial[blockIdx.y][i * HDIM];
#pragma unroll
    for (int q = 0; q < 8; q++)
        outp[q] = make_float4(acc[2*q].x, acc[2*q].y, acc[2*q+1].x, acc[2*q+1].y);
}

// ---------------- reduce + net_out fused ----------------
__global__ void k_netout(const float* __restrict__ W1, const float* __restrict__ b1,
                         const float* __restrict__ W2, const float* __restrict__ b2) {
    __shared__ float sW1[HDIM * HDIM], sW2[HDIM * HDIM], sb1[HDIM], sb2[HDIM];
    int tid = threadIdx.x;
    for (int k = tid; k < HDIM * HDIM; k += TILE_I) { sW1[k] = W1[k]; sW2[k] = W2[k]; }
    if (tid < HDIM) { sb1[tid] = b1[tid]; sb2[tid] = b2[tid]; }
    __syncthreads();

    int n = blockIdx.x * TILE_I + tid;

    float xi[HDIM];
#pragma unroll
    for (int h = 0; h < HDIM; h++) xi[h] = 0.f;
    for (int p = 0; p < JSPLIT; p++) {
        const float4* v = (const float4*)&g_partial[p][n * HDIM];
#pragma unroll
        for (int q = 0; q < 8; q++) {
            float4 t = v[q];
            xi[4*q]   += t.x; xi[4*q+1] += t.y;
            xi[4*q+2] += t.z; xi[4*q+3] += t.w;
        }
    }

    float z1[HDIM];
#pragma unroll
    for (int h = 0; h < HDIM; h++) {
        float acc = sb1[h];
#pragma unroll
        for (int c = 0; c < HDIM; c++) acc = fmaf(sW1[h * HDIM + c], xi[c], acc);
        z1[h] = leakyf(acc);
    }
#pragma unroll
    for (int h = 0; h < HDIM; h++) {
        float acc = sb2[h];
#pragma unroll
        for (int c = 0; c < HDIM; c++) acc = fmaf(sW2[h * HDIM + c], z1[c], acc);
        g_z[n * HDIM + h] = leakyf(acc);
    }
}

// ---------------- launch ----------------
extern "C" void kernel_launch(void* const* d_in, const int* in_sizes, int n_in,
                              void* d_out, int out_size) {
    const float* points  = (const float*)d_in[0];
    const float* nuv     = (const float*)d_in[1];
    const float* feats   = (const float*)d_in[2];
    const float* W_in1   = (const float*)d_in[3];
    const float* b_in1   = (const float*)d_in[4];
    const float* W_in2   = (const float*)d_in[5];
    const float* b_in2   = (const float*)d_in[6];
    const float* g_in_w  = (const float*)d_in[7];
    const float* g_in_b  = (const float*)d_in[8];
    const float* A1      = (const float*)d_in[9];
    const float* A2      = (const float*)d_in[10];
    const float* W_out1  = (const float*)d_in[11];
    const float* b_out1  = (const float*)d_in[12];
    const float* W_out2  = (const float*)d_in[13];
    const float* b_out2  = (const float*)d_in[14];
    const float* g_out_w = (const float*)d_in[15];
    const float* g_out_b = (const float*)d_in[16];
    const float* B1      = (const float*)d_in[17];
    const float* B2      = (const float*)d_in[18];

    float* p_z;
    cudaGetSymbolAddress((void**)&p_z, g_z);

    k_netin<<<NPTS / TILE_I, TILE_I>>>(points, nuv, feats, W_in1, b_in1, W_in2, b_in2);
    k_gstats<<<1, 1024>>>(p_z);
    k_pair<<<dim3(NPTS / TILE_I, JSPLIT), TILE_I>>>(nuv, A1, B1, A2, B2, g_in_w, g_in_b);
    k_netout<<<NPTS / TILE_I, TILE_I>>>(W_out1, b_out1, W_out2, b_out2);
    k_gstats<<<1, 1024>>>(p_z);
    k_gnorm<<<(NPTS * HDIM) / 256, 256>>>(p_z, g_out_w, g_out_b, (float*)d_out);
}

// round 3
// speedup vs baseline: 2.2698x; 2.2698x over previous
#include <cuda_runtime.h>
#include <math.h>

#define NPTS   2048
#define IDIM   16
#define HDIM   32
#define JSPLIT 9
#define JCHUNK 228          // 8*228 + 224 = 2048
#define TILE_I 128

// ---------------- device scratch ----------------
__device__ float4 g_pts4[NPTS];
__device__ float4 g_nrm4[NPTS];
__device__ float  g_z   [NPTS * HDIM];
__device__ float  g_partial[JSPLIT][NPTS * HDIM];
__device__ float  g_stats[8];   // mu[0..3], rstd[4..7]

__device__ __forceinline__ float leakyf(float x) { return x >= 0.f ? x : 0.2f * x; }

// ---------------- net_in + prep fused ----------------
__global__ void k_netin(const float* __restrict__ points, const float* __restrict__ nuv,
                        const float* __restrict__ x,
                        const float* __restrict__ W1, const float* __restrict__ b1,
                        const float* __restrict__ W2, const float* __restrict__ b2) {
    __shared__ float sW1[HDIM * IDIM], sW2[HDIM * HDIM], sb1[HDIM], sb2[HDIM];
    int tid = threadIdx.x;
    for (int k = tid; k < HDIM * IDIM; k += TILE_I) sW1[k] = W1[k];
    for (int k = tid; k < HDIM * HDIM; k += TILE_I) sW2[k] = W2[k];
    if (tid < HDIM) { sb1[tid] = b1[tid]; sb2[tid] = b2[tid]; }
    __syncthreads();

    int n = blockIdx.x * TILE_I + tid;

    const float s = 0.07856742013183862f;  // 1/(sqrt(2)*9)
    g_pts4[n] = make_float4(points[n * 3] * s, points[n * 3 + 1] * s, points[n * 3 + 2] * s, 0.f);
    g_nrm4[n] = make_float4(nuv[n * 9], nuv[n * 9 + 1], nuv[n * 9 + 2], 0.f);

    float xi[IDIM];
#pragma unroll
    for (int i = 0; i < IDIM; i++) xi[i] = x[n * IDIM + i];

    float z1[HDIM];
#pragma unroll
    for (int h = 0; h < HDIM; h++) {
        float acc = sb1[h];
#pragma unroll
        for (int i = 0; i < IDIM; i++) acc = fmaf(sW1[h * IDIM + i], xi[i], acc);
        z1[h] = leakyf(acc);
    }
#pragma unroll
    for (int h = 0; h < HDIM; h++) {
        float acc = sb2[h];
#pragma unroll
        for (int c = 0; c < HDIM; c++) acc = fmaf(sW2[h * HDIM + c], z1[c], acc);
        g_z[n * HDIM + h] = leakyf(acc);
    }
}

// ---------------- group-norm stats (coalesced, 1024 threads, 1 block) ----------------
__global__ void k_gstats(const float* __restrict__ z) {
    __shared__ double sh_s[1024], sh_q[1024];
    int tid = threadIdx.x;
    int c = tid & 31;
    int r0 = tid >> 5;
    double s = 0.0, q = 0.0;
    for (int it = 0; it < NPTS / 32; it++) {
        float v = z[(r0 + 32 * it) * HDIM + c];
        s += (double)v;
        q += (double)v * (double)v;
    }
    sh_s[tid] = s; sh_q[tid] = q;
    __syncthreads();
    if (tid < 32) {
        double S = 0.0, Q = 0.0;
        for (int m = 0; m < 32; m++) { S += sh_s[tid + 32 * m]; Q += sh_q[tid + 32 * m]; }
        sh_s[tid] = S; sh_q[tid] = Q;
    }
    __syncthreads();
    if (tid < 4) {
        double S = 0.0, Q = 0.0;
        for (int cc = tid * 8; cc < tid * 8 + 8; cc++) { S += sh_s[cc]; Q += sh_q[cc]; }
        double cntd = (double)NPTS * 8.0;
        double mu = S / cntd;
        double var = Q / cntd - mu * mu;
        g_stats[tid]     = (float)mu;
        g_stats[4 + tid] = (float)(1.0 / sqrt(var + 1e-5));
    }
}

// ---------------- apply group norm (final output only) ----------------
__global__ void k_gnorm(const float* __restrict__ z, const float* __restrict__ gamma,
                        const float* __restrict__ beta, float* __restrict__ out) {
    int idx = blockIdx.x * blockDim.x + threadIdx.x;
    if (idx >= NPTS * HDIM) return;
    int c = idx & (HDIM - 1);
    int g = c >> 3;
    out[idx] = (z[idx] - g_stats[g]) * g_stats[4 + g] * gamma[c] + beta[c];
}

// ---------------- pairwise interaction: 64 i x 2 h-halves per block ----------------
// A2/B2 register-resident (16 h-rows per thread). LDS per j ~ 14 vs R1's 96.
__global__ void __launch_bounds__(TILE_I, 2)
k_pair(const float* __restrict__ nuv,
       const float* __restrict__ A1, const float* __restrict__ B1,
       const float* __restrict__ A2, const float* __restrict__ B2,
       const float* __restrict__ gamma, const float* __restrict__ beta) {
    __shared__ float4 sP[JCHUNK], sN[JCHUNK];
    __shared__ float  sF[JCHUNK][HDIM];
    __shared__ float4 sA1[8];          // (a1x, a1y, a1z, b1) per cut
    __shared__ float  smu[4], srs[4];

    int tid = threadIdx.x;
    int j0  = blockIdx.y * JCHUNK;
    int cnt = min(JCHUNK, NPTS - j0);

    if (tid < 4)              { smu[tid] = g_stats[tid]; srs[tid] = g_stats[4 + tid]; }
    if (tid >= 8 && tid < 16) { int c = tid - 8; sA1[c] = make_float4(A1[c*3], A1[c*3+1], A1[c*3+2], B1[c]); }
    __syncthreads();   // smu/srs visible

    for (int k = tid; k < cnt; k += TILE_I) { sP[k] = g_pts4[j0 + k]; sN[k] = g_nrm4[j0 + k]; }
    for (int k = tid; k < cnt * HDIM; k += TILE_I) {
        int r = k >> 5, c = k & 31, g = c >> 3;
        sF[r][c] = (g_z[(j0 + r) * HDIM + c] - smu[g]) * srs[g] * gamma[c] + beta[c];
    }
    __syncthreads();

    int half  = tid >> 6;            // 0 or 1
    int iloc  = tid & 63;
    int i     = blockIdx.x * 64 + iloc;
    int hbase = half * 16;

    float4 p4 = g_pts4[i];
    float4 n4 = g_nrm4[i];
    float u[9];
#pragma unroll
    for (int k = 0; k < 9; k++) u[k] = nuv[i * 9 + k];

    // register-resident A2 slab: rows [hbase, hbase+16)
    float a2r[16][8], b2r[16];
#pragma unroll
    for (int h = 0; h < 16; h++) {
        b2r[h] = B2[hbase + h];
#pragma unroll
        for (int c = 0; c < 8; c++) a2r[h][c] = A2[(hbase + h) * 8 + c];
    }

    float acc[16];
#pragma unroll
    for (int h = 0; h < 16; h++) acc[h] = 0.f;

    for (int j = 0; j < cnt; j++) {
        float4 pj = sP[j], nj = sN[j];
        float dx = pj.x - p4.x, dy = pj.y - p4.y, dz = pj.z - p4.z;
        float sq  = fmaf(dx, dx, fmaf(dy, dy, dz * dz));
        float dot = fmaf(n4.x, nj.x, fmaf(n4.y, nj.y, n4.z * nj.z));
        float t   = 2.f - dot;
        float w   = __expf(-(sq * t) * t);

        float X0 = fmaf(u[0], dx, fmaf(u[1], dy, u[2] * dz));
        float X1 = fmaf(u[3], dx, fmaf(u[4], dy, u[5] * dz));
        float X2 = fmaf(u[6], dx, fmaf(u[7], dy, u[8] * dz));

        float xc[8];
#pragma unroll
        for (int c = 0; c < 8; c++) {
            float4 a = sA1[c];
            float s = fmaf(a.x, X0, fmaf(a.y, X1, fmaf(a.z, X2, a.w)));
            xc[c] = fmaxf(s, 0.f);
        }

        const float4* frow = (const float4*)sF[j];
#pragma unroll
        for (int q = 0; q < 4; q++) {
            float4 f4 = frow[half * 4 + q];
            float wf0 = w * f4.x, wf1 = w * f4.y, wf2 = w * f4.z, wf3 = w * f4.w;
#pragma unroll
            for (int r = 0; r < 4; r++) {
                int h = q * 4 + r;
                float s = b2r[h];
#pragma unroll
                for (int c = 0; c < 8; c++) s = fmaf(a2r[h][c], xc[c], s);
                s = fmaxf(s, 0.f);
                float wf = (r == 0) ? wf0 : (r == 1) ? wf1 : (r == 2) ? wf2 : wf3;
                acc[h] = fmaf(s, wf, acc[h]);
            }
        }
    }

    float4* outp = (float4*)&g_partial[blockIdx.y][i * HDIM + hbase];
#pragma unroll
    for (int q = 0; q < 4; q++)
        outp[q] = make_float4(acc[4*q], acc[4*q+1], acc[4*q+2], acc[4*q+3]);
}

// ---------------- reduce(9 partials) + net_out fused ----------------
__global__ void k_netout(const float* __restrict__ W1, const float* __restrict__ b1,
                         const float* __restrict__ W2, const float* __restrict__ b2) {
    __shared__ float sW1[HDIM * HDIM], sW2[HDIM * HDIM], sb1[HDIM], sb2[HDIM];
    int tid = threadIdx.x;
    for (int k = tid; k < HDIM * HDIM; k += TILE_I) { sW1[k] = W1[k]; sW2[k] = W2[k]; }
    if (tid < HDIM) { sb1[tid] = b1[tid]; sb2[tid] = b2[tid]; }
    __syncthreads();

    int n = blockIdx.x * TILE_I + tid;

    float xi[HDIM];
#pragma unroll
    for (int h = 0; h < HDIM; h++) xi[h] = 0.f;
#pragma unroll
    for (int p = 0; p < JSPLIT; p++) {
        const float4* v = (const float4*)&g_partial[p][n * HDIM];
#pragma unroll
        for (int q = 0; q < 8; q++) {
            float4 t = v[q];
            xi[4*q]   += t.x; xi[4*q+1] += t.y;
            xi[4*q+2] += t.z; xi[4*q+3] += t.w;
        }
    }

    float z1[HDIM];
#pragma unroll
    for (int h = 0; h < HDIM; h++) {
        float acc = sb1[h];
#pragma unroll
        for (int c = 0; c < HDIM; c++) acc = fmaf(sW1[h * HDIM + c], xi[c], acc);
        z1[h] = leakyf(acc);
    }
#pragma unroll
    for (int h = 0; h < HDIM; h++) {
        float acc = sb2[h];
#pragma unroll
        for (int c = 0; c < HDIM; c++) acc = fmaf(sW2[h * HDIM + c], z1[c], acc);
        g_z[n * HDIM + h] = leakyf(acc);
    }
}

// ---------------- launch ----------------
extern "C" void kernel_launch(void* const* d_in, const int* in_sizes, int n_in,
                              void* d_out, int out_size) {
    const float* points  = (const float*)d_in[0];
    const float* nuv     = (const float*)d_in[1];
    const float* feats   = (const float*)d_in[2];
    const float* W_in1   = (const float*)d_in[3];
    const float* b_in1   = (const float*)d_in[4];
    const float* W_in2   = (const float*)d_in[5];
    const float* b_in2   = (const float*)d_in[6];
    const float* g_in_w  = (const float*)d_in[7];
    const float* g_in_b  = (const float*)d_in[8];
    const float* A1      = (const float*)d_in[9];
    const float* A2      = (const float*)d_in[10];
    const float* W_out1  = (const float*)d_in[11];
    const float* b_out1  = (const float*)d_in[12];
    const float* W_out2  = (const float*)d_in[13];
    const float* b_out2  = (const float*)d_in[14];
    const float* g_out_w = (const float*)d_in[15];
    const float* g_out_b = (const float*)d_in[16];
    const float* B1      = (const float*)d_in[17];
    const float* B2      = (const float*)d_in[18];

    float* p_z;
    cudaGetSymbolAddress((void**)&p_z, g_z);

    k_netin<<<NPTS / TILE_I, TILE_I>>>(points, nuv, feats, W_in1, b_in1, W_in2, b_in2);
    k_gstats<<<1, 1024>>>(p_z);
    k_pair<<<dim3(NPTS / 64, JSPLIT), TILE_I>>>(nuv, A1, B1, A2, B2, g_in_w, g_in_b);
    k_netout<<<NPTS / TILE_I, TILE_I>>>(W_out1, b_out1, W_out2, b_out2);
    k_gstats<<<1, 1024>>>(p_z);
    k_gnorm<<<(NPTS * HDIM) / 256, 256>>>(p_z, g_out_w, g_out_b, (float*)d_out);
}